// round 13
// baseline (speedup 1.0000x reference)
#include <cuda_runtime.h>
#include <math_constants.h>
#include <cstdint>

#define BB 128
#define TT 2048
#define HH 256
#define OUTD 128

#define NCHUNK 8                          // chunks per batch
#define ROWS_PER_CTA (TT / NCHUNK)        // 256 rows
#define NPART (BB * NCHUNK)               // 1024

#define K1_THREADS 128                    // 4 warps
#define K1_WARPS 4
#define ROWS_PER_WARP (ROWS_PER_CTA / K1_WARPS)   // 64
#define STAGE_ROWS 4
#define STAGE_BYTES (STAGE_ROWS * HH * 4) // 4096
#define NSTAGE 4
#define ITERS (ROWS_PER_WARP / STAGE_ROWS) // 16

// dynamic smem layout (bytes)
#define OFF_TILES 0
#define SZ_TILES  (K1_WARPS * NSTAGE * STAGE_BYTES)    // 65536
#define OFF_ACC   (OFF_TILES + SZ_TILES)               // 65536
#define SZ_ACC    (K1_WARPS * HH * 4)                  // 4096
#define OFF_WM    (OFF_ACC + SZ_ACC)                   // 69632
#define OFF_WZ    (OFF_WM + 16)
#define OFF_BARS  (OFF_WZ + 16)                        // 69664 (8-aligned)
#define SMEM_K1   (OFF_BARS + K1_WARPS * NSTAGE * 8)   // 69792 -> 3 CTAs/SM

// Global scratch (allocation-free)
__device__ float g_v[BB * HH];
__device__ float g_m[NPART];
__device__ float g_z[NPART];
__device__ float g_acc[NPART * HH];
__device__ unsigned int g_flagB[BB] = {}; // per-batch v-ready; reset by k2

// ---------------- PTX helpers ----------------
__device__ __forceinline__ uint32_t s2u(const void* p) {
    uint32_t a;
    asm("{ .reg .u64 t; cvta.to.shared.u64 t, %1; cvt.u32.u64 %0, t; }"
        : "=r"(a) : "l"(p));
    return a;
}
__device__ __forceinline__ void mbar_init(uint32_t bar, uint32_t cnt) {
    asm volatile("mbarrier.init.shared.b64 [%0], %1;" :: "r"(bar), "r"(cnt) : "memory");
}
__device__ __forceinline__ void mbar_expect_tx(uint32_t bar, uint32_t bytes) {
    asm volatile("mbarrier.arrive.expect_tx.shared.b64 _, [%0], %1;"
                 :: "r"(bar), "r"(bytes) : "memory");
}
__device__ __forceinline__ void mbar_wait(uint32_t bar, uint32_t parity) {
    uint32_t done;
    asm volatile(
        "{ .reg .pred p; mbarrier.try_wait.parity.acquire.cta.shared::cta.b64 p, [%1], %2; "
        "selp.b32 %0, 1, 0, p; }" : "=r"(done) : "r"(bar), "r"(parity) : "memory");
    while (!done) {
        asm volatile(
            "{ .reg .pred p; mbarrier.try_wait.parity.acquire.cta.shared::cta.b64 p, [%1], %2, 0x989680; "
            "selp.b32 %0, 1, 0, p; }" : "=r"(done) : "r"(bar), "r"(parity) : "memory");
    }
}
__device__ __forceinline__ void bulk_copy_g2s(uint32_t dst_smem, const void* src,
                                              uint32_t bytes, uint32_t mbar) {
    asm volatile(
        "cp.async.bulk.shared::cta.global.mbarrier::complete_tx::bytes [%0], [%1], %2, [%3];"
        :: "r"(dst_smem), "l"(src), "r"(bytes), "r"(mbar) : "memory");
}
__device__ __forceinline__ void fence_async_shared() {
    asm volatile("fence.proxy.async.shared::cta;" ::: "memory");
}
__device__ __forceinline__ void pdl_wait() {
    asm volatile("griddepcontrol.wait;" ::: "memory");
}
__device__ __forceinline__ void pdl_launch_dependents() {
    asm volatile("griddepcontrol.launch_dependents;" ::: "memory");
}
__device__ __forceinline__ unsigned int ld_acquire_gpu(const unsigned int* p) {
    unsigned int v;
    asm volatile("ld.acquire.gpu.global.u32 %0, [%1];" : "=r"(v) : "l"(p) : "memory");
    return v;
}
__device__ __forceinline__ void red_release_add(unsigned int* p, unsigned int v) {
    asm volatile("red.release.gpu.global.add.u32 [%0], %1;" :: "l"(p), "r"(v) : "memory");
}

// ---------------------------------------------------------------------------
// kernel1: fused v-compute (per-batch leader) + per-warp bulk-async streaming.
//   grid = 1024 CTAs x 128 thr, 3 CTAs/SM.
//   CTA b*8 (chunk 0) computes v_b = W_score @ h_t[b] after issuing its
//   prologue copies, then releases g_flagB[b]. Its 7 siblings spin-acquire
//   that flag only (pairwise, no global rendezvous). Leader bid < sibling
//   bids -> leader scheduled no later than spinners -> guaranteed progress.
// ---------------------------------------------------------------------------
__global__ __launch_bounds__(K1_THREADS, 3)
void k1_stream(const float* __restrict__ hidden,
               const float* __restrict__ Wscore)
{
    extern __shared__ __align__(128) unsigned char smem_raw[];
    float* s_tiles = (float*)(smem_raw + OFF_TILES);
    float* s_acc   = (float*)(smem_raw + OFF_ACC);
    float* s_wm    = (float*)(smem_raw + OFF_WM);
    float* s_wz    = (float*)(smem_raw + OFF_WZ);

    const int cta   = blockIdx.x;
    const int b     = cta >> 3;               // / NCHUNK
    const int chunk = cta & (NCHUNK - 1);
    const int tid   = threadIdx.x, w = tid >> 5, lane = tid & 31;

    const uint32_t bar0  = s2u(smem_raw + OFF_BARS) + w * NSTAGE * 8;
    const uint32_t tile0 = s2u(smem_raw) + w * NSTAGE * STAGE_BYTES;
    float* tbase = s_tiles + w * NSTAGE * (STAGE_ROWS * HH);

    const float* src = hidden
        + ((size_t)b * TT + chunk * ROWS_PER_CTA + w * ROWS_PER_WARP) * HH;

    // per-warp barrier init + prologue copies -- issued FIRST so the memory
    // system streams while v is computed / awaited
    if (lane == 0) {
        #pragma unroll
        for (int s = 0; s < NSTAGE; s++) mbar_init(bar0 + s * 8, 1);
        fence_async_shared();
        #pragma unroll
        for (int s = 0; s < NSTAGE; s++) {
            mbar_expect_tx(bar0 + s * 8, STAGE_BYTES);
            bulk_copy_g2s(tile0 + s * STAGE_BYTES,
                          src + (size_t)s * STAGE_ROWS * HH,
                          STAGE_BYTES, bar0 + s * 8);
        }
    }
    __syncwarp();

    if (chunk == 0) {
        // ---- leader: compute v_b. ht register-resident; warp w covers
        //      h = 64w..64w+63, 4 rows per iter, 16 independent iters ----
        const float* hp = hidden + ((size_t)b * TT + (TT - 1)) * HH;
        const float4 h0 = *(const float4*)(hp + lane * 4);
        const float4 h1 = *(const float4*)(hp + 128 + lane * 4);

        for (int it = 0; it < 16; it++) {
            const int h = w * 64 + it * 4;
            const float* wp = Wscore + (size_t)h * HH;
            float4 W0[4], W1[4];
            #pragma unroll
            for (int r = 0; r < 4; r++) {
                W0[r] = *(const float4*)(wp + (size_t)r * HH + lane * 4);
                W1[r] = *(const float4*)(wp + (size_t)r * HH + 128 + lane * 4);
            }
            float s0 = W0[0].x*h0.x + W0[0].y*h0.y + W0[0].z*h0.z + W0[0].w*h0.w
                     + W1[0].x*h1.x + W1[0].y*h1.y + W1[0].z*h1.z + W1[0].w*h1.w;
            float s1 = W0[1].x*h0.x + W0[1].y*h0.y + W0[1].z*h0.z + W0[1].w*h0.w
                     + W1[1].x*h1.x + W1[1].y*h1.y + W1[1].z*h1.z + W1[1].w*h1.w;
            float s2 = W0[2].x*h0.x + W0[2].y*h0.y + W0[2].z*h0.z + W0[2].w*h0.w
                     + W1[2].x*h1.x + W1[2].y*h1.y + W1[2].z*h1.z + W1[2].w*h1.w;
            float s3 = W0[3].x*h0.x + W0[3].y*h0.y + W0[3].z*h0.z + W0[3].w*h0.w
                     + W1[3].x*h1.x + W1[3].y*h1.y + W1[3].z*h1.z + W1[3].w*h1.w;
            #pragma unroll
            for (int off = 16; off; off >>= 1) {
                s0 += __shfl_xor_sync(0xffffffffu, s0, off);
                s1 += __shfl_xor_sync(0xffffffffu, s1, off);
                s2 += __shfl_xor_sync(0xffffffffu, s2, off);
                s3 += __shfl_xor_sync(0xffffffffu, s3, off);
            }
            const float val = (lane == 0) ? s0 : (lane == 1) ? s1
                            : (lane == 2) ? s2 : s3;
            if (lane < 4) g_v[b * HH + h + lane] = val;
        }
        __syncthreads();                  // all 4 warps' g_v stores done
        if (tid == 0) {
            __threadfence();
            red_release_add(&g_flagB[b], 1);
        }
    } else {
        // ---- sibling: wait for this batch's v only ----
        if (tid == 0) {
            while (ld_acquire_gpu(&g_flagB[b]) == 0) __nanosleep(64);
        }
        __syncthreads();
    }

    const float4 v0 = *(const float4*)(g_v + b * HH + lane * 4);
    const float4 v1 = *(const float4*)(g_v + b * HH + 128 + lane * 4);

    float  m = -CUDART_INF_F, Z = 0.f;
    float4 a0 = make_float4(0.f, 0.f, 0.f, 0.f);
    float4 a1 = make_float4(0.f, 0.f, 0.f, 0.f);

    for (int i = 0; i < ITERS; i++) {
        const int s = i & (NSTAGE - 1);
        mbar_wait(bar0 + s * 8, (i >> 2) & 1);

        const float* tp = tbase + s * (STAGE_ROWS * HH);
        float4 x[STAGE_ROWS][2];
        #pragma unroll
        for (int r = 0; r < STAGE_ROWS; r++) {
            x[r][0] = *(const float4*)(tp + r * HH + lane * 4);
            x[r][1] = *(const float4*)(tp + r * HH + 128 + lane * 4);
        }

        // consume the registers first (score FMAs)...
        float sc[STAGE_ROWS];
        #pragma unroll
        for (int r = 0; r < STAGE_ROWS; r++) {
            sc[r] = x[r][0].x * v0.x + x[r][0].y * v0.y + x[r][0].z * v0.z + x[r][0].w * v0.w
                  + x[r][1].x * v1.x + x[r][1].y * v1.y + x[r][1].z * v1.z + x[r][1].w * v1.w;
        }

        // ...then refill stage s (all lanes' LDS done per __syncwarp)
        __syncwarp();
        if (lane == 0 && i + NSTAGE < ITERS) {
            mbar_expect_tx(bar0 + s * 8, STAGE_BYTES);
            bulk_copy_g2s(tile0 + s * STAGE_BYTES,
                          src + (size_t)(i + NSTAGE) * STAGE_ROWS * HH,
                          STAGE_BYTES, bar0 + s * 8);
        }

        #pragma unroll
        for (int off = 16; off; off >>= 1) {
            #pragma unroll
            for (int r = 0; r < STAGE_ROWS; r++)
                sc[r] += __shfl_xor_sync(0xffffffffu, sc[r], off);
        }
        const float mc = fmaxf(fmaxf(sc[0], sc[1]), fmaxf(sc[2], sc[3]));
        if (mc > m) {                          // warp-uniform
            const float rr = __expf(m - mc);   // first stage: exp(-inf)=0
            Z *= rr;
            a0.x *= rr; a0.y *= rr; a0.z *= rr; a0.w *= rr;
            a1.x *= rr; a1.y *= rr; a1.z *= rr; a1.w *= rr;
            m = mc;
        }
        #pragma unroll
        for (int r = 0; r < STAGE_ROWS; r++) {
            const float p = __expf(sc[r] - m);
            Z += p;
            a0.x += p * x[r][0].x; a0.y += p * x[r][0].y;
            a0.z += p * x[r][0].z; a0.w += p * x[r][0].w;
            a1.x += p * x[r][1].x; a1.y += p * x[r][1].y;
            a1.z += p * x[r][1].z; a1.w += p * x[r][1].w;
        }
    }

    // intra-CTA combine (4 warps)
    if (lane == 0) { s_wm[w] = m; s_wz[w] = Z; }
    *(float4*)(&s_acc[w * HH + lane * 4])       = a0;
    *(float4*)(&s_acc[w * HH + 128 + lane * 4]) = a1;
    __syncthreads();

    const float M = fmaxf(fmaxf(s_wm[0], s_wm[1]), fmaxf(s_wm[2], s_wm[3]));
    const float e0 = __expf(s_wm[0] - M), e1 = __expf(s_wm[1] - M);
    const float e2 = __expf(s_wm[2] - M), e3 = __expf(s_wm[3] - M);

    if (tid == 0) {
        g_m[cta] = M;
        g_z[cta] = e0 * s_wz[0] + e1 * s_wz[1] + e2 * s_wz[2] + e3 * s_wz[3];
    }
    #pragma unroll
    for (int jj = 0; jj < 2; jj++) {
        const int ch = tid + jj * 128;
        g_acc[(size_t)cta * HH + ch] =
            e0 * s_acc[0 * HH + ch] + e1 * s_acc[1 * HH + ch]
          + e2 * s_acc[2 * HH + ch] + e3 * s_acc[3 * HH + ch];
    }
    pdl_launch_dependents();
}

// ---------------------------------------------------------------------------
// kernel2: merge partials -> ctx; out = tanh(concat(ctx,h_t) @ W_att).
//          grid = 16 CTAs x 8 batches, 512 thr. CTA 0 resets g_flagB.
// ---------------------------------------------------------------------------
__global__ __launch_bounds__(512)
void k2_combine(const float* __restrict__ hidden,
                const float* __restrict__ Watt,
                float* __restrict__ out)
{
    __shared__ float s_pre[8][2 * HH];   // 16KB
    __shared__ float s_e[8][NCHUNK];
    __shared__ float s_Z[8];
    __shared__ float sW[32 * OUTD];      // 16KB W_att tile

    const int b0 = blockIdx.x * 8;
    const int tid = threadIdx.x;

    pdl_wait();                          // k1 fully done

    if (blockIdx.x == 0 && tid < BB) g_flagB[tid] = 0;   // reset for replay

    if (tid < 8 * NCHUNK) {              // stash m values
        const int bi = tid >> 3, p = tid & 7;
        s_e[bi][p] = g_m[(b0 + bi) * NCHUNK + p];
    }
    __syncthreads();
    if (tid < 8) {
        float M = -CUDART_INF_F;
        #pragma unroll
        for (int p = 0; p < NCHUNK; p++) M = fmaxf(M, s_e[tid][p]);
        float Zt = 0.f;
        #pragma unroll
        for (int p = 0; p < NCHUNK; p++) {
            const float e = __expf(s_e[tid][p] - M);
            Zt += e * g_z[(b0 + tid) * NCHUNK + p];
            s_e[tid][p] = e;
        }
        s_Z[tid] = Zt;
    }
    __syncthreads();

    const int bi = tid >> 6, c0 = tid & 63;
    #pragma unroll
    for (int cc = 0; cc < 4; cc++) {
        const int ch = c0 + cc * 64;
        float c = 0.f;
        #pragma unroll
        for (int p = 0; p < NCHUNK; p++)
            c += s_e[bi][p] * g_acc[(size_t)((b0 + bi) * NCHUNK + p) * HH + ch];
        s_pre[bi][ch]      = c / s_Z[bi];
        s_pre[bi][HH + ch] = hidden[((size_t)(b0 + bi) * TT + (TT - 1)) * HH + ch];
    }
    __syncthreads();

    // out[bi][j], 2 outputs per thread; W_att tiled 32 rows at a time via smem
    const int j = tid & 63;
    float acc0 = 0.f, acc1 = 0.f;
    for (int t = 0; t < 16; t++) {
        #pragma unroll
        for (int q = 0; q < 8; q++)      // 512 thr load 32x128 = 4096 floats
            sW[tid + q * 512] = Watt[(t * 32) * OUTD + tid + q * 512];
        __syncthreads();
        #pragma unroll
        for (int i = 0; i < 32; i++) {
            const float p = s_pre[bi][t * 32 + i];
            acc0 += p * sW[i * OUTD + j];
            acc1 += p * sW[i * OUTD + j + 64];
        }
        __syncthreads();
    }
    out[(b0 + bi) * OUTD + j]      = tanhf(acc0);
    out[(b0 + bi) * OUTD + j + 64] = tanhf(acc1);
}

extern "C" void kernel_launch(void* const* d_in, const int* in_sizes, int n_in,
                              void* d_out, int out_size) {
    const float* hidden = (const float*)d_in[0];   // (128, 2048, 256) f32
    const float* Wscore = (const float*)d_in[1];   // (256, 256) f32
    const float* Watt   = (const float*)d_in[2];   // (512, 128) f32
    float* out = (float*)d_out;                    // (128, 128) f32

    cudaFuncSetAttribute(k1_stream, cudaFuncAttributeMaxDynamicSharedMemorySize, SMEM_K1);

    k1_stream<<<BB * NCHUNK, K1_THREADS, SMEM_K1>>>(hidden, Wscore);

    cudaLaunchAttribute pdl_attr;
    pdl_attr.id = cudaLaunchAttributeProgrammaticStreamSerialization;
    pdl_attr.val.programmaticStreamSerializationAllowed = 1;

    {   // k2 with PDL
        cudaLaunchConfig_t cfg = {};
        cfg.gridDim = dim3(16);
        cfg.blockDim = dim3(512);
        cfg.dynamicSmemBytes = 0;
        cfg.stream = 0;
        cfg.attrs = &pdl_attr;
        cfg.numAttrs = 1;
        cudaLaunchKernelEx(&cfg, k2_combine, hidden, Watt, out);
    }
}

// round 14
// speedup vs baseline: 1.1564x; 1.1564x over previous
#include <cuda_runtime.h>
#include <math_constants.h>
#include <cstdint>

#define BB 128
#define TT 2048
#define HH 256
#define OUTD 128

#define NCHUNK 16                         // chunks per batch
#define ROWS_PER_CTA (TT / NCHUNK)        // 128 rows
#define NPART (BB * NCHUNK)               // 2048

#define K1_THREADS 128                    // 4 warps
#define K1_WARPS 4
#define ROWS_PER_WARP (ROWS_PER_CTA / K1_WARPS)   // 32
#define STAGE_ROWS 4
#define STAGE_BYTES (STAGE_ROWS * HH * 4) // 4096
#define NSTAGE 4
#define ITERS (ROWS_PER_WARP / STAGE_ROWS) // 8

// dynamic smem layout (bytes)
#define OFF_TILES 0
#define SZ_TILES  (K1_WARPS * NSTAGE * STAGE_BYTES)    // 65536
#define OFF_ACC   (OFF_TILES + SZ_TILES)               // 65536
#define SZ_ACC    (K1_WARPS * HH * 4)                  // 4096
#define OFF_WM    (OFF_ACC + SZ_ACC)                   // 69632
#define OFF_WZ    (OFF_WM + 16)
#define OFF_BARS  (OFF_WZ + 16)                        // 69664 (8-aligned)
#define SMEM_K1   (OFF_BARS + K1_WARPS * NSTAGE * 8)   // 69792 -> 3 CTAs/SM

// Global scratch (allocation-free)
__device__ float g_v[BB * HH];
__device__ float g_m[NPART];
__device__ float g_z[NPART];
__device__ float g_acc[NPART * HH];       // 2MB

// ---------------- PTX helpers ----------------
__device__ __forceinline__ uint32_t s2u(const void* p) {
    uint32_t a;
    asm("{ .reg .u64 t; cvta.to.shared.u64 t, %1; cvt.u32.u64 %0, t; }"
        : "=r"(a) : "l"(p));
    return a;
}
__device__ __forceinline__ void mbar_init(uint32_t bar, uint32_t cnt) {
    asm volatile("mbarrier.init.shared.b64 [%0], %1;" :: "r"(bar), "r"(cnt) : "memory");
}
__device__ __forceinline__ void mbar_expect_tx(uint32_t bar, uint32_t bytes) {
    asm volatile("mbarrier.arrive.expect_tx.shared.b64 _, [%0], %1;"
                 :: "r"(bar), "r"(bytes) : "memory");
}
__device__ __forceinline__ void mbar_wait(uint32_t bar, uint32_t parity) {
    uint32_t done;
    asm volatile(
        "{ .reg .pred p; mbarrier.try_wait.parity.acquire.cta.shared::cta.b64 p, [%1], %2; "
        "selp.b32 %0, 1, 0, p; }" : "=r"(done) : "r"(bar), "r"(parity) : "memory");
    while (!done) {
        asm volatile(
            "{ .reg .pred p; mbarrier.try_wait.parity.acquire.cta.shared::cta.b64 p, [%1], %2, 0x989680; "
            "selp.b32 %0, 1, 0, p; }" : "=r"(done) : "r"(bar), "r"(parity) : "memory");
    }
}
__device__ __forceinline__ void bulk_copy_g2s(uint32_t dst_smem, const void* src,
                                              uint32_t bytes, uint32_t mbar) {
    asm volatile(
        "cp.async.bulk.shared::cta.global.mbarrier::complete_tx::bytes [%0], [%1], %2, [%3];"
        :: "r"(dst_smem), "l"(src), "r"(bytes), "r"(mbar) : "memory");
}
__device__ __forceinline__ void fence_async_shared() {
    asm volatile("fence.proxy.async.shared::cta;" ::: "memory");
}
__device__ __forceinline__ void pdl_wait() {
    asm volatile("griddepcontrol.wait;" ::: "memory");
}
__device__ __forceinline__ void pdl_launch_dependents() {
    asm volatile("griddepcontrol.launch_dependents;" ::: "memory");
}

// ---------------------------------------------------------------------------
// kernel0: V[b,h] = sum_k W_score[h,k]*ht[b,k]   (R11 version, proven)
//   grid = (16 b-groups x 16 h-groups) = 256 CTAs, 256 thr.
// ---------------------------------------------------------------------------
__global__ __launch_bounds__(256)
void k0_compute_v(const float* __restrict__ hidden,
                  const float* __restrict__ Wscore)
{
    __shared__ float s_ht[8][HH];
    const int b0 = blockIdx.x * 8;
    const int h0 = blockIdx.y * 16;
    const int tid = threadIdx.x, w = tid >> 5, lane = tid & 31;

    // warp w loads ht row for batch b0+w
    {
        const float* hp = hidden + ((size_t)(b0 + w) * TT + (TT - 1)) * HH;
        *(float4*)&s_ht[w][lane * 4]       = *(const float4*)(hp + lane * 4);
        *(float4*)&s_ht[w][128 + lane * 4] = *(const float4*)(hp + 128 + lane * 4);
    }
    // W rows h0+2w, h0+2w+1 in registers (lane's 8 channels)
    const int h = h0 + w * 2;
    const float* w0p = Wscore + (size_t)h * HH;
    const float4 wa0 = *(const float4*)(w0p + lane * 4);
    const float4 wa1 = *(const float4*)(w0p + 128 + lane * 4);
    const float4 wb0 = *(const float4*)(w0p + HH + lane * 4);
    const float4 wb1 = *(const float4*)(w0p + HH + 128 + lane * 4);
    __syncthreads();

    float o0 = 0.f, o1 = 0.f;
    #pragma unroll
    for (int b = 0; b < 8; b++) {
        const float4 x0 = *(const float4*)&s_ht[b][lane * 4];
        const float4 x1 = *(const float4*)&s_ht[b][128 + lane * 4];
        float s0 = wa0.x * x0.x + wa0.y * x0.y + wa0.z * x0.z + wa0.w * x0.w
                 + wa1.x * x1.x + wa1.y * x1.y + wa1.z * x1.z + wa1.w * x1.w;
        float s1 = wb0.x * x0.x + wb0.y * x0.y + wb0.z * x0.z + wb0.w * x0.w
                 + wb1.x * x1.x + wb1.y * x1.y + wb1.z * x1.z + wb1.w * x1.w;
        #pragma unroll
        for (int off = 16; off; off >>= 1) {
            s0 += __shfl_xor_sync(0xffffffffu, s0, off);
            s1 += __shfl_xor_sync(0xffffffffu, s1, off);
        }
        if (lane == b) { o0 = s0; o1 = s1; }
    }
    if (lane < 8) {
        g_v[(b0 + lane) * HH + h]     = o0;
        g_v[(b0 + lane) * HH + h + 1] = o1;
    }
    pdl_launch_dependents();
}

// ---------------------------------------------------------------------------
// kernel1: per-warp self-paced bulk-async pipeline.
//   grid = 2048 CTAs x 128 thr, 3 CTAs/SM — halved CTA size vs R11 to
//   shrink the ramp-down tail (tail waste ~ T_c/2; T_c halves).
// ---------------------------------------------------------------------------
__global__ __launch_bounds__(K1_THREADS, 3)
void k1_stream(const float* __restrict__ hidden)
{
    extern __shared__ __align__(128) unsigned char smem_raw[];
    float* s_tiles = (float*)(smem_raw + OFF_TILES);
    float* s_acc   = (float*)(smem_raw + OFF_ACC);
    float* s_wm    = (float*)(smem_raw + OFF_WM);
    float* s_wz    = (float*)(smem_raw + OFF_WZ);

    const int cta   = blockIdx.x;
    const int b     = cta >> 4;               // / NCHUNK
    const int chunk = cta & (NCHUNK - 1);
    const int tid   = threadIdx.x, w = tid >> 5, lane = tid & 31;

    const uint32_t bar0  = s2u(smem_raw + OFF_BARS) + w * NSTAGE * 8;
    const uint32_t tile0 = s2u(smem_raw) + w * NSTAGE * STAGE_BYTES;
    float* tbase = s_tiles + w * NSTAGE * (STAGE_ROWS * HH);

    const float* src = hidden
        + ((size_t)b * TT + chunk * ROWS_PER_CTA + w * ROWS_PER_WARP) * HH;

    // per-warp barrier init + prologue copies (independent of g_v -> overlaps k0)
    if (lane == 0) {
        #pragma unroll
        for (int s = 0; s < NSTAGE; s++) mbar_init(bar0 + s * 8, 1);
        fence_async_shared();
        #pragma unroll
        for (int s = 0; s < NSTAGE; s++) {
            mbar_expect_tx(bar0 + s * 8, STAGE_BYTES);
            bulk_copy_g2s(tile0 + s * STAGE_BYTES,
                          src + (size_t)s * STAGE_ROWS * HH,
                          STAGE_BYTES, bar0 + s * 8);
        }
    }
    __syncwarp();

    // PDL: g_v produced by k0 -- wait here, after the copies are in flight
    pdl_wait();

    const float4 v0 = *(const float4*)(g_v + b * HH + lane * 4);
    const float4 v1 = *(const float4*)(g_v + b * HH + 128 + lane * 4);

    float  m = -CUDART_INF_F, Z = 0.f;
    float4 a0 = make_float4(0.f, 0.f, 0.f, 0.f);
    float4 a1 = make_float4(0.f, 0.f, 0.f, 0.f);

    for (int i = 0; i < ITERS; i++) {
        const int s = i & (NSTAGE - 1);
        mbar_wait(bar0 + s * 8, (i >> 2) & 1);

        const float* tp = tbase + s * (STAGE_ROWS * HH);
        float4 x[STAGE_ROWS][2];
        #pragma unroll
        for (int r = 0; r < STAGE_ROWS; r++) {
            x[r][0] = *(const float4*)(tp + r * HH + lane * 4);
            x[r][1] = *(const float4*)(tp + r * HH + 128 + lane * 4);
        }

        // consume the registers first (score FMAs)...
        float sc[STAGE_ROWS];
        #pragma unroll
        for (int r = 0; r < STAGE_ROWS; r++) {
            sc[r] = x[r][0].x * v0.x + x[r][0].y * v0.y + x[r][0].z * v0.z + x[r][0].w * v0.w
                  + x[r][1].x * v1.x + x[r][1].y * v1.y + x[r][1].z * v1.z + x[r][1].w * v1.w;
        }

        // ...then refill stage s (all lanes' LDS done per __syncwarp)
        __syncwarp();
        if (lane == 0 && i + NSTAGE < ITERS) {
            mbar_expect_tx(bar0 + s * 8, STAGE_BYTES);
            bulk_copy_g2s(tile0 + s * STAGE_BYTES,
                          src + (size_t)(i + NSTAGE) * STAGE_ROWS * HH,
                          STAGE_BYTES, bar0 + s * 8);
        }

        #pragma unroll
        for (int off = 16; off; off >>= 1) {
            #pragma unroll
            for (int r = 0; r < STAGE_ROWS; r++)
                sc[r] += __shfl_xor_sync(0xffffffffu, sc[r], off);
        }
        const float mc = fmaxf(fmaxf(sc[0], sc[1]), fmaxf(sc[2], sc[3]));
        if (mc > m) {                          // warp-uniform
            const float rr = __expf(m - mc);   // first stage: exp(-inf)=0
            Z *= rr;
            a0.x *= rr; a0.y *= rr; a0.z *= rr; a0.w *= rr;
            a1.x *= rr; a1.y *= rr; a1.z *= rr; a1.w *= rr;
            m = mc;
        }
        #pragma unroll
        for (int r = 0; r < STAGE_ROWS; r++) {
            const float p = __expf(sc[r] - m);
            Z += p;
            a0.x += p * x[r][0].x; a0.y += p * x[r][0].y;
            a0.z += p * x[r][0].z; a0.w += p * x[r][0].w;
            a1.x += p * x[r][1].x; a1.y += p * x[r][1].y;
            a1.z += p * x[r][1].z; a1.w += p * x[r][1].w;
        }
    }

    // intra-CTA combine (4 warps)
    if (lane == 0) { s_wm[w] = m; s_wz[w] = Z; }
    *(float4*)(&s_acc[w * HH + lane * 4])       = a0;
    *(float4*)(&s_acc[w * HH + 128 + lane * 4]) = a1;
    __syncthreads();

    const float M = fmaxf(fmaxf(s_wm[0], s_wm[1]), fmaxf(s_wm[2], s_wm[3]));
    const float e0 = __expf(s_wm[0] - M), e1 = __expf(s_wm[1] - M);
    const float e2 = __expf(s_wm[2] - M), e3 = __expf(s_wm[3] - M);

    if (tid == 0) {
        g_m[cta] = M;
        g_z[cta] = e0 * s_wz[0] + e1 * s_wz[1] + e2 * s_wz[2] + e3 * s_wz[3];
    }
    #pragma unroll
    for (int jj = 0; jj < 2; jj++) {
        const int ch = tid + jj * 128;
        g_acc[(size_t)cta * HH + ch] =
            e0 * s_acc[0 * HH + ch] + e1 * s_acc[1 * HH + ch]
          + e2 * s_acc[2 * HH + ch] + e3 * s_acc[3 * HH + ch];
    }
    pdl_launch_dependents();
}

// ---------------------------------------------------------------------------
// kernel2: merge 16 partials/batch -> ctx; out = tanh(concat(ctx,ht) @ W_att)
//          grid = 16 CTAs x 8 batches, 512 thr, W_att staged through smem.
// ---------------------------------------------------------------------------
__global__ __launch_bounds__(512)
void k2_combine(const float* __restrict__ hidden,
                const float* __restrict__ Watt,
                float* __restrict__ out)
{
    __shared__ float s_pre[8][2 * HH];   // 16KB
    __shared__ float s_e[8][NCHUNK];     // 8 x 16
    __shared__ float s_Z[8];
    __shared__ float sW[32 * OUTD];      // 16KB W_att tile

    const int b0 = blockIdx.x * 8;
    const int tid = threadIdx.x;

    pdl_wait();                          // k1 partials must be complete

    if (tid < 8 * NCHUNK) {              // stash m values
        const int bi = tid >> 4, p = tid & 15;
        s_e[bi][p] = g_m[(b0 + bi) * NCHUNK + p];
    }
    __syncthreads();
    if (tid < 8) {
        float M = -CUDART_INF_F;
        #pragma unroll
        for (int p = 0; p < NCHUNK; p++) M = fmaxf(M, s_e[tid][p]);
        float Zt = 0.f;
        #pragma unroll
        for (int p = 0; p < NCHUNK; p++) {
            const float e = __expf(s_e[tid][p] - M);
            Zt += e * g_z[(b0 + tid) * NCHUNK + p];
            s_e[tid][p] = e;
        }
        s_Z[tid] = Zt;
    }
    __syncthreads();

    const int bi = tid >> 6, c0 = tid & 63;
    #pragma unroll
    for (int cc = 0; cc < 4; cc++) {
        const int ch = c0 + cc * 64;
        float c = 0.f;
        #pragma unroll
        for (int p = 0; p < NCHUNK; p++)
            c += s_e[bi][p] * g_acc[(size_t)((b0 + bi) * NCHUNK + p) * HH + ch];
        s_pre[bi][ch]      = c / s_Z[bi];
        s_pre[bi][HH + ch] = hidden[((size_t)(b0 + bi) * TT + (TT - 1)) * HH + ch];
    }
    __syncthreads();

    // out[bi][j], 2 outputs per thread; W_att tiled 32 rows at a time via smem
    const int j = tid & 63;
    float acc0 = 0.f, acc1 = 0.f;
    for (int t = 0; t < 16; t++) {
        #pragma unroll
        for (int q = 0; q < 8; q++)      // 512 thr load 32x128 = 4096 floats
            sW[tid + q * 512] = Watt[(t * 32) * OUTD + tid + q * 512];
        __syncthreads();
        #pragma unroll
        for (int i = 0; i < 32; i++) {
            const float p = s_pre[bi][t * 32 + i];
            acc0 += p * sW[i * OUTD + j];
            acc1 += p * sW[i * OUTD + j + 64];
        }
        __syncthreads();
    }
    out[(b0 + bi) * OUTD + j]      = tanhf(acc0);
    out[(b0 + bi) * OUTD + j + 64] = tanhf(acc1);
}

extern "C" void kernel_launch(void* const* d_in, const int* in_sizes, int n_in,
                              void* d_out, int out_size) {
    const float* hidden = (const float*)d_in[0];   // (128, 2048, 256) f32
    const float* Wscore = (const float*)d_in[1];   // (256, 256) f32
    const float* Watt   = (const float*)d_in[2];   // (512, 128) f32
    float* out = (float*)d_out;                    // (128, 128) f32

    cudaFuncSetAttribute(k1_stream, cudaFuncAttributeMaxDynamicSharedMemorySize, SMEM_K1);

    k0_compute_v<<<dim3(BB / 8, HH / 16), 256>>>(hidden, Wscore);

    cudaLaunchAttribute pdl_attr;
    pdl_attr.id = cudaLaunchAttributeProgrammaticStreamSerialization;
    pdl_attr.val.programmaticStreamSerializationAllowed = 1;

    {   // k1 with PDL
        cudaLaunchConfig_t cfg = {};
        cfg.gridDim = dim3(BB * NCHUNK);
        cfg.blockDim = dim3(K1_THREADS);
        cfg.dynamicSmemBytes = SMEM_K1;
        cfg.stream = 0;
        cfg.attrs = &pdl_attr;
        cfg.numAttrs = 1;
        cudaLaunchKernelEx(&cfg, k1_stream, hidden);
    }
    {   // k2 with PDL
        cudaLaunchConfig_t cfg = {};
        cfg.gridDim = dim3(16);
        cfg.blockDim = dim3(512);
        cfg.dynamicSmemBytes = 0;
        cfg.stream = 0;
        cfg.attrs = &pdl_attr;
        cfg.numAttrs = 1;
        cudaLaunchKernelEx(&cfg, k2_combine, hidden, Watt, out);
    }
}

// round 16
// speedup vs baseline: 1.4450x; 1.2496x over previous
#include <cuda_runtime.h>
#include <math_constants.h>
#include <cstdint>

#define BB 128
#define TT 2048
#define HH 256
#define OUTD 128

#define NCHUNK 8                          // chunks per batch
#define ROWS_PER_CTA (TT / NCHUNK)        // 256 rows
#define NPART (BB * NCHUNK)               // 1024

#define K1_THREADS 128                    // 4 warps
#define K1_WARPS 4
#define ROWS_PER_WARP (ROWS_PER_CTA / K1_WARPS)   // 64
#define STAGE_ROWS 4
#define STAGE_BYTES (STAGE_ROWS * HH * 4) // 4096
#define NSTAGE 4
#define ITERS (ROWS_PER_WARP / STAGE_ROWS) // 16

// dynamic smem layout (bytes)
#define OFF_TILES 0
#define SZ_TILES  (K1_WARPS * NSTAGE * STAGE_BYTES)    // 65536
#define OFF_ACC   (OFF_TILES + SZ_TILES)               // 65536
#define SZ_ACC    (K1_WARPS * HH * 4)                  // 4096
#define OFF_WM    (OFF_ACC + SZ_ACC)                   // 69632
#define OFF_WZ    (OFF_WM + 16)
#define OFF_BARS  (OFF_WZ + 16)                        // 69664 (8-aligned)
#define SMEM_K1   (OFF_BARS + K1_WARPS * NSTAGE * 8)   // 69792 -> 3 CTAs/SM

// Global scratch (allocation-free)
__device__ float g_v[BB * HH];
__device__ float g_m[NPART];
__device__ float g_z[NPART];
__device__ float g_acc[NPART * HH];

// ---------------- PTX helpers ----------------
__device__ __forceinline__ uint32_t s2u(const void* p) {
    uint32_t a;
    asm("{ .reg .u64 t; cvta.to.shared.u64 t, %1; cvt.u32.u64 %0, t; }"
        : "=r"(a) : "l"(p));
    return a;
}
__device__ __forceinline__ void mbar_init(uint32_t bar, uint32_t cnt) {
    asm volatile("mbarrier.init.shared.b64 [%0], %1;" :: "r"(bar), "r"(cnt) : "memory");
}
__device__ __forceinline__ void mbar_expect_tx(uint32_t bar, uint32_t bytes) {
    asm volatile("mbarrier.arrive.expect_tx.shared.b64 _, [%0], %1;"
                 :: "r"(bar), "r"(bytes) : "memory");
}
__device__ __forceinline__ void mbar_wait(uint32_t bar, uint32_t parity) {
    uint32_t done;
    asm volatile(
        "{ .reg .pred p; mbarrier.try_wait.parity.acquire.cta.shared::cta.b64 p, [%1], %2; "
        "selp.b32 %0, 1, 0, p; }" : "=r"(done) : "r"(bar), "r"(parity) : "memory");
    while (!done) {
        asm volatile(
            "{ .reg .pred p; mbarrier.try_wait.parity.acquire.cta.shared::cta.b64 p, [%1], %2, 0x989680; "
            "selp.b32 %0, 1, 0, p; }" : "=r"(done) : "r"(bar), "r"(parity) : "memory");
    }
}
__device__ __forceinline__ void bulk_copy_g2s(uint32_t dst_smem, const void* src,
                                              uint32_t bytes, uint32_t mbar) {
    asm volatile(
        "cp.async.bulk.shared::cta.global.mbarrier::complete_tx::bytes [%0], [%1], %2, [%3];"
        :: "r"(dst_smem), "l"(src), "r"(bytes), "r"(mbar) : "memory");
}
__device__ __forceinline__ void fence_async_shared() {
    asm volatile("fence.proxy.async.shared::cta;" ::: "memory");
}
__device__ __forceinline__ void pdl_wait() {
    asm volatile("griddepcontrol.wait;" ::: "memory");
}
__device__ __forceinline__ void pdl_launch_dependents() {
    asm volatile("griddepcontrol.launch_dependents;" ::: "memory");
}

// ---------------------------------------------------------------------------
// kernel0: V[b,h] = sum_k W_score[h,k]*ht[b,k]
//   grid = (16 b-groups x 16 h-groups) = 256 CTAs, 256 thr.
//   launch_dependents fires AT ENTRY: k1 launches concurrently, issues its
//   hidden-prologue copies, and its pdl_wait blocks until this grid COMPLETES
//   (g_v visible). Overlap instead of serialization.
// ---------------------------------------------------------------------------
__global__ __launch_bounds__(256)
void k0_compute_v(const float* __restrict__ hidden,
                  const float* __restrict__ Wscore)
{
    pdl_launch_dependents();             // earliest possible dependent launch

    __shared__ float s_ht[8][HH];
    const int b0 = blockIdx.x * 8;
    const int h0 = blockIdx.y * 16;
    const int tid = threadIdx.x, w = tid >> 5, lane = tid & 31;

    // warp w loads ht row for batch b0+w
    {
        const float* hp = hidden + ((size_t)(b0 + w) * TT + (TT - 1)) * HH;
        *(float4*)&s_ht[w][lane * 4]       = *(const float4*)(hp + lane * 4);
        *(float4*)&s_ht[w][128 + lane * 4] = *(const float4*)(hp + 128 + lane * 4);
    }
    // W rows h0+2w, h0+2w+1 in registers (lane's 8 channels)
    const int h = h0 + w * 2;
    const float* w0p = Wscore + (size_t)h * HH;
    const float4 wa0 = *(const float4*)(w0p + lane * 4);
    const float4 wa1 = *(const float4*)(w0p + 128 + lane * 4);
    const float4 wb0 = *(const float4*)(w0p + HH + lane * 4);
    const float4 wb1 = *(const float4*)(w0p + HH + 128 + lane * 4);
    __syncthreads();

    float o0 = 0.f, o1 = 0.f;
    #pragma unroll
    for (int b = 0; b < 8; b++) {
        const float4 x0 = *(const float4*)&s_ht[b][lane * 4];
        const float4 x1 = *(const float4*)&s_ht[b][128 + lane * 4];
        float s0 = wa0.x * x0.x + wa0.y * x0.y + wa0.z * x0.z + wa0.w * x0.w
                 + wa1.x * x1.x + wa1.y * x1.y + wa1.z * x1.z + wa1.w * x1.w;
        float s1 = wb0.x * x0.x + wb0.y * x0.y + wb0.z * x0.z + wb0.w * x0.w
                 + wb1.x * x1.x + wb1.y * x1.y + wb1.z * x1.z + wb1.w * x1.w;
        #pragma unroll
        for (int off = 16; off; off >>= 1) {
            s0 += __shfl_xor_sync(0xffffffffu, s0, off);
            s1 += __shfl_xor_sync(0xffffffffu, s1, off);
        }
        if (lane == b) { o0 = s0; o1 = s1; }   // compile-time b -> no spill
    }
    if (lane < 8) {
        g_v[(b0 + lane) * HH + h]     = o0;
        g_v[(b0 + lane) * HH + h + 1] = o1;
    }
}

// ---------------------------------------------------------------------------
// kernel1: per-warp self-paced bulk-async pipeline (R11 config: 4 stages x
//          4KB, occ 3). grid = 1024 CTAs x 128 thr. Prologue copies overlap
//          k0; pdl_wait only before reading g_v.
// ---------------------------------------------------------------------------
__global__ __launch_bounds__(K1_THREADS, 3)
void k1_stream(const float* __restrict__ hidden)
{
    extern __shared__ __align__(128) unsigned char smem_raw[];
    float* s_tiles = (float*)(smem_raw + OFF_TILES);
    float* s_acc   = (float*)(smem_raw + OFF_ACC);
    float* s_wm    = (float*)(smem_raw + OFF_WM);
    float* s_wz    = (float*)(smem_raw + OFF_WZ);

    const int cta   = blockIdx.x;
    const int b     = cta >> 3;               // / NCHUNK
    const int chunk = cta & (NCHUNK - 1);
    const int tid   = threadIdx.x, w = tid >> 5, lane = tid & 31;

    const uint32_t bar0  = s2u(smem_raw + OFF_BARS) + w * NSTAGE * 8;
    const uint32_t tile0 = s2u(smem_raw) + w * NSTAGE * STAGE_BYTES;
    float* tbase = s_tiles + w * NSTAGE * (STAGE_ROWS * HH);

    const float* src = hidden
        + ((size_t)b * TT + chunk * ROWS_PER_CTA + w * ROWS_PER_WARP) * HH;

    pdl_launch_dependents();             // k2 may launch; it pdl_waits anyway

    // per-warp barrier init + prologue copies (independent of g_v -> overlaps k0)
    if (lane == 0) {
        #pragma unroll
        for (int s = 0; s < NSTAGE; s++) mbar_init(bar0 + s * 8, 1);
        fence_async_shared();
        #pragma unroll
        for (int s = 0; s < NSTAGE; s++) {
            mbar_expect_tx(bar0 + s * 8, STAGE_BYTES);
            bulk_copy_g2s(tile0 + s * STAGE_BYTES,
                          src + (size_t)s * STAGE_ROWS * HH,
                          STAGE_BYTES, bar0 + s * 8);
        }
    }
    __syncwarp();

    // PDL: g_v produced by k0 -- wait here, after the copies are in flight
    pdl_wait();

    const float4 v0 = *(const float4*)(g_v + b * HH + lane * 4);
    const float4 v1 = *(const float4*)(g_v + b * HH + 128 + lane * 4);

    float  m = -CUDART_INF_F, Z = 0.f;
    float4 a0 = make_float4(0.f, 0.f, 0.f, 0.f);
    float4 a1 = make_float4(0.f, 0.f, 0.f, 0.f);

    for (int i = 0; i < ITERS; i++) {
        const int s = i & (NSTAGE - 1);
        mbar_wait(bar0 + s * 8, (i >> 2) & 1);

        const float* tp = tbase + s * (STAGE_ROWS * HH);
        float4 x[STAGE_ROWS][2];
        #pragma unroll
        for (int r = 0; r < STAGE_ROWS; r++) {
            x[r][0] = *(const float4*)(tp + r * HH + lane * 4);
            x[r][1] = *(const float4*)(tp + r * HH + 128 + lane * 4);
        }

        // consume the registers first (score FMAs)...
        float sc[STAGE_ROWS];
        #pragma unroll
        for (int r = 0; r < STAGE_ROWS; r++) {
            sc[r] = x[r][0].x * v0.x + x[r][0].y * v0.y + x[r][0].z * v0.z + x[r][0].w * v0.w
                  + x[r][1].x * v1.x + x[r][1].y * v1.y + x[r][1].z * v1.z + x[r][1].w * v1.w;
        }

        // ...then refill stage s (all lanes' LDS done per __syncwarp)
        __syncwarp();
        if (lane == 0 && i + NSTAGE < ITERS) {
            mbar_expect_tx(bar0 + s * 8, STAGE_BYTES);
            bulk_copy_g2s(tile0 + s * STAGE_BYTES,
                          src + (size_t)(i + NSTAGE) * STAGE_ROWS * HH,
                          STAGE_BYTES, bar0 + s * 8);
        }

        #pragma unroll
        for (int off = 16; off; off >>= 1) {
            #pragma unroll
            for (int r = 0; r < STAGE_ROWS; r++)
                sc[r] += __shfl_xor_sync(0xffffffffu, sc[r], off);
        }
        const float mc = fmaxf(fmaxf(sc[0], sc[1]), fmaxf(sc[2], sc[3]));
        if (mc > m) {                          // warp-uniform
            const float rr = __expf(m - mc);   // first stage: exp(-inf)=0
            Z *= rr;
            a0.x *= rr; a0.y *= rr; a0.z *= rr; a0.w *= rr;
            a1.x *= rr; a1.y *= rr; a1.z *= rr; a1.w *= rr;
            m = mc;
        }
        #pragma unroll
        for (int r = 0; r < STAGE_ROWS; r++) {
            const float p = __expf(sc[r] - m);
            Z += p;
            a0.x += p * x[r][0].x; a0.y += p * x[r][0].y;
            a0.z += p * x[r][0].z; a0.w += p * x[r][0].w;
            a1.x += p * x[r][1].x; a1.y += p * x[r][1].y;
            a1.z += p * x[r][1].z; a1.w += p * x[r][1].w;
        }
    }

    // intra-CTA combine (4 warps)
    if (lane == 0) { s_wm[w] = m; s_wz[w] = Z; }
    *(float4*)(&s_acc[w * HH + lane * 4])       = a0;
    *(float4*)(&s_acc[w * HH + 128 + lane * 4]) = a1;
    __syncthreads();

    const float M = fmaxf(fmaxf(s_wm[0], s_wm[1]), fmaxf(s_wm[2], s_wm[3]));
    const float e0 = __expf(s_wm[0] - M), e1 = __expf(s_wm[1] - M);
    const float e2 = __expf(s_wm[2] - M), e3 = __expf(s_wm[3] - M);

    if (tid == 0) {
        g_m[cta] = M;
        g_z[cta] = e0 * s_wz[0] + e1 * s_wz[1] + e2 * s_wz[2] + e3 * s_wz[3];
    }
    #pragma unroll
    for (int jj = 0; jj < 2; jj++) {
        const int ch = tid + jj * 128;
        g_acc[(size_t)cta * HH + ch] =
            e0 * s_acc[0 * HH + ch] + e1 * s_acc[1 * HH + ch]
          + e2 * s_acc[2 * HH + ch] + e3 * s_acc[3 * HH + ch];
    }
}

// ---------------------------------------------------------------------------
// kernel2: merge partials -> ctx; out = tanh(concat(ctx,h_t) @ W_att).
//          grid = 16 CTAs x 8 batches, 512 thr, W_att staged through smem.
// ---------------------------------------------------------------------------
__global__ __launch_bounds__(512)
void k2_combine(const float* __restrict__ hidden,
                const float* __restrict__ Watt,
                float* __restrict__ out)
{
    __shared__ float s_pre[8][2 * HH];   // 16KB
    __shared__ float s_e[8][NCHUNK];
    __shared__ float s_Z[8];
    __shared__ float sW[32 * OUTD];      // 16KB W_att tile

    const int b0 = blockIdx.x * 8;
    const int tid = threadIdx.x;

    pdl_wait();                          // k1 partials must be complete

    if (tid < 8 * NCHUNK) {              // stash m values
        const int bi = tid >> 3, p = tid & 7;
        s_e[bi][p] = g_m[(b0 + bi) * NCHUNK + p];
    }
    __syncthreads();
    if (tid < 8) {
        float M = -CUDART_INF_F;
        #pragma unroll
        for (int p = 0; p < NCHUNK; p++) M = fmaxf(M, s_e[tid][p]);
        float Zt = 0.f;
        #pragma unroll
        for (int p = 0; p < NCHUNK; p++) {
            const float e = __expf(s_e[tid][p] - M);
            Zt += e * g_z[(b0 + tid) * NCHUNK + p];
            s_e[tid][p] = e;
        }
        s_Z[tid] = Zt;
    }
    __syncthreads();

    const int bi = tid >> 6, c0 = tid & 63;
    #pragma unroll
    for (int cc = 0; cc < 4; cc++) {
        const int ch = c0 + cc * 64;
        float c = 0.f;
        #pragma unroll
        for (int p = 0; p < NCHUNK; p++)
            c += s_e[bi][p] * g_acc[(size_t)((b0 + bi) * NCHUNK + p) * HH + ch];
        s_pre[bi][ch]      = c / s_Z[bi];
        s_pre[bi][HH + ch] = hidden[((size_t)(b0 + bi) * TT + (TT - 1)) * HH + ch];
    }
    __syncthreads();

    // out[bi][j], 2 outputs per thread; W_att tiled 32 rows at a time via smem
    const int j = tid & 63;
    float acc0 = 0.f, acc1 = 0.f;
    for (int t = 0; t < 16; t++) {
        #pragma unroll
        for (int q = 0; q < 8; q++)      // 512 thr load 32x128 = 4096 floats
            sW[tid + q * 512] = Watt[(t * 32) * OUTD + tid + q * 512];
        __syncthreads();
        #pragma unroll
        for (int i = 0; i < 32; i++) {
            const float p = s_pre[bi][t * 32 + i];
            acc0 += p * sW[i * OUTD + j];
            acc1 += p * sW[i * OUTD + j + 64];
        }
        __syncthreads();
    }
    out[(b0 + bi) * OUTD + j]      = tanhf(acc0);
    out[(b0 + bi) * OUTD + j + 64] = tanhf(acc1);
}

extern "C" void kernel_launch(void* const* d_in, const int* in_sizes, int n_in,
                              void* d_out, int out_size) {
    const float* hidden = (const float*)d_in[0];   // (128, 2048, 256) f32
    const float* Wscore = (const float*)d_in[1];   // (256, 256) f32
    const float* Watt   = (const float*)d_in[2];   // (512, 128) f32
    float* out = (float*)d_out;                    // (128, 128) f32

    cudaFuncSetAttribute(k1_stream, cudaFuncAttributeMaxDynamicSharedMemorySize, SMEM_K1);

    k0_compute_v<<<dim3(BB / 8, HH / 16), 256>>>(hidden, Wscore);

    cudaLaunchAttribute pdl_attr;
    pdl_attr.id = cudaLaunchAttributeProgrammaticStreamSerialization;
    pdl_attr.val.programmaticStreamSerializationAllowed = 1;

    {   // k1 with PDL
        cudaLaunchConfig_t cfg = {};
        cfg.gridDim = dim3(BB * NCHUNK);
        cfg.blockDim = dim3(K1_THREADS);
        cfg.dynamicSmemBytes = SMEM_K1;
        cfg.stream = 0;
        cfg.attrs = &pdl_attr;
        cfg.numAttrs = 1;
        cudaLaunchKernelEx(&cfg, k1_stream, hidden);
    }
    {   // k2 with PDL
        cudaLaunchConfig_t cfg = {};
        cfg.gridDim = dim3(16);
        cfg.blockDim = dim3(512);
        cfg.dynamicSmemBytes = 0;
        cfg.stream = 0;
        cfg.attrs = &pdl_attr;
        cfg.numAttrs = 1;
        cudaLaunchKernelEx(&cfg, k2_combine, hidden, Watt, out);
    }
}